// round 1
// baseline (speedup 1.0000x reference)
#include <cuda_runtime.h>

// Fused local NCC loss, kernel=3, zero 'same' padding, 192^3 f32 volumes.
// Strategy: lanes along d (coalesced), thread fixed (h,d), march along w with a
// 3-deep register ring of plane-sums of {I, J, I*I, J*J, I*J} over the 3x3 (h,d)
// neighborhood. Each plane loaded once per thread -> 18 LDG per output voxel.

#define SZ   192
#define SZ2  (192 * 192)
#define NTOT (192 * 192 * 192)
#define CHUNK 24                  // w outputs per block
#define GX 3                      // d tiles  (3 * 64  = 192)
#define GY 48                     // h groups (48 * 4  = 192)
#define GZ 8                      // w chunks (8 * 24  = 192)
#define NBLK (GX * GY * GZ)       // 1152

__device__ float g_partial[NBLK];

__global__ __launch_bounds__(256, 8)
void lncc_main_kernel(const float* __restrict__ pred,
                      const float* __restrict__ targ) {
    const int d  = blockIdx.x * 64 + threadIdx.x;   // 0..191, lanes contiguous in d
    const int h  = blockIdx.y * 4  + threadIdx.y;   // 0..191
    const int w0 = blockIdx.z * CHUNK;

    const bool dm = (d > 0);
    const bool dp = (d < SZ - 1);
    const bool hm = (h > 0);
    const bool hp = (h < SZ - 1);

    // ring: a = ps(wp-2), b = ps(wp-1); 5 components each
    float a0 = 0.f, a1 = 0.f, a2 = 0.f, a3 = 0.f, a4 = 0.f;
    float b0 = 0.f, b1 = 0.f, b2 = 0.f, b3 = 0.f, b4 = 0.f;
    float acc = 0.f;

    for (int wp = w0 - 1; wp <= w0 + CHUNK; ++wp) {
        float c0 = 0.f, c1 = 0.f, c2 = 0.f, c3 = 0.f, c4 = 0.f;
        if (wp >= 0 && wp < SZ) {
            const int base = wp * SZ + d;
            #pragma unroll
            for (int dh = -1; dh <= 1; ++dh) {
                if (dh == -1 && !hm) continue;
                if (dh ==  1 && !hp) continue;
                const int hh = h + dh;
                const float* pb = pred + hh * SZ2 + base;
                const float* tb = targ + hh * SZ2 + base;
                {   // center d
                    float I = pb[0], J = tb[0];
                    c0 += I; c1 += J;
                    c2 = fmaf(I, I, c2); c3 = fmaf(J, J, c3); c4 = fmaf(I, J, c4);
                }
                if (dm) {
                    float I = pb[-1], J = tb[-1];
                    c0 += I; c1 += J;
                    c2 = fmaf(I, I, c2); c3 = fmaf(J, J, c3); c4 = fmaf(I, J, c4);
                }
                if (dp) {
                    float I = pb[1], J = tb[1];
                    c0 += I; c1 += J;
                    c2 = fmaf(I, I, c2); c3 = fmaf(J, J, c3); c4 = fmaf(I, J, c4);
                }
            }
        }
        // output voxel at w = wp - 1 (needs planes wp-2, wp-1, wp)
        if (wp - 1 >= w0) {   // wp-1 < w0+CHUNK always holds in this loop
            float sI  = a0 + b0 + c0;
            float sJ  = a1 + b1 + c1;
            float sII = a2 + b2 + c2;
            float sJJ = a3 + b3 + c3;
            float sIJ = a4 + b4 + c4;
            const float inv_kv = 1.0f / 27.0f;
            float uI = sI * inv_kv;
            float uJ = sJ * inv_kv;
            float cross = sIJ - uJ * sI;    // sum((I-uI)(J-uJ))
            float Ivar  = sII - uI * sI;    // sum((I-uI)^2)
            float Jvar  = sJJ - uJ * sJ;    // sum((J-uJ)^2)
            float ncc = (cross * cross) / (Ivar * Jvar + 1e-5f);
            acc += ncc;
        }
        a0 = b0; a1 = b1; a2 = b2; a3 = b3; a4 = b4;
        b0 = c0; b1 = c1; b2 = c2; b3 = c3; b4 = c4;
    }

    // deterministic block reduction
    __shared__ float red[256];
    const int tid = threadIdx.y * 64 + threadIdx.x;
    red[tid] = acc;
    __syncthreads();
    #pragma unroll
    for (int s = 128; s > 0; s >>= 1) {
        if (tid < s) red[tid] += red[tid + s];
        __syncthreads();
    }
    if (tid == 0) {
        const int blin = blockIdx.x + GX * (blockIdx.y + GY * blockIdx.z);
        g_partial[blin] = red[0];
    }
}

__global__ void lncc_final_kernel(float* __restrict__ out) {
    __shared__ double red[256];
    double s = 0.0;
    for (int i = threadIdx.x; i < NBLK; i += 256)
        s += (double)g_partial[i];
    red[threadIdx.x] = s;
    __syncthreads();
    #pragma unroll
    for (int k = 128; k > 0; k >>= 1) {
        if (threadIdx.x < k) red[threadIdx.x] += red[threadIdx.x + k];
        __syncthreads();
    }
    if (threadIdx.x == 0)
        out[0] = (float)(-red[0] / (double)NTOT);
}

extern "C" void kernel_launch(void* const* d_in, const int* in_sizes, int n_in,
                              void* d_out, int out_size) {
    const float* pred = (const float*)d_in[0];
    const float* targ = (const float*)d_in[1];
    dim3 grid(GX, GY, GZ);
    dim3 block(64, 4, 1);
    lncc_main_kernel<<<grid, block>>>(pred, targ);
    lncc_final_kernel<<<1, 256>>>((float*)d_out);
}

// round 2
// speedup vs baseline: 1.8041x; 1.8041x over previous
#include <cuda_runtime.h>

// Fused local NCC loss (kernel=3, zero 'same' padding) over 192^3 f32 volumes.
// Separable plan per thread: lane = d (coalesced, center-only loads),
// h handled by a 4-output register row-block (6 rows incl. halo),
// d-sum via warp shuffles (warps overlap: 32 lanes -> 30 d outputs),
// w handled by marching with a 3-slot ring (unroll-3, no reg moves).
// Final mean folded in via deterministic last-block reduction.

#define SZ   192
#define SZ2  (SZ * SZ)
#define NTOT (SZ * SZ * SZ)

#define D_OUT  30            // d outputs per warp (lanes 1..30)
#define GX     7             // ceil(192/30)
#define H_OUT  4             // h outputs per thread
#define BY     4             // h-groups per block -> h tile 16
#define GY     12            // 192 / 16
#define WCHUNK 16            // w outputs per block
#define GZ     12            // 192 / 16
#define NBLK   (GX * GY * GZ) // 1008

__device__ float        g_partial[NBLK];
__device__ unsigned int g_count = 0;

__device__ __forceinline__ void compute_plane(
    const float* __restrict__ pred, const float* __restrict__ targ,
    int base0, int wp, unsigned hmask, bool dok, float (&C)[H_OUT][5])
{
#pragma unroll
    for (int j = 0; j < H_OUT; j++)
#pragma unroll
        for (int k = 0; k < 5; k++) C[j][k] = 0.f;
    if ((unsigned)wp >= (unsigned)SZ) return;

    float rp[6][5];
    const int pbase = base0 + wp * SZ;
#pragma unroll
    for (int i = 0; i < 6; i++) {
        float I = 0.f, J = 0.f;
        if (((hmask >> i) & 1u) && dok) {
            int off = pbase + i * SZ2;
            I = pred[off];
            J = targ[off];
        }
        rp[i][0] = I;     rp[i][1] = J;
        rp[i][2] = I * I; rp[i][3] = J * J; rp[i][4] = I * J;
    }
#pragma unroll
    for (int k = 0; k < 5; k++) {
        float t0 = rp[0][k] + rp[1][k];
        float t1 = rp[1][k] + rp[2][k];
        float t2 = rp[2][k] + rp[3][k];
        float t3 = rp[3][k] + rp[4][k];
        float s0 = t0 + rp[2][k];
        float s1 = t1 + rp[3][k];
        float s2 = t2 + rp[4][k];
        float s3 = t3 + rp[5][k];
        C[0][k] = s0 + __shfl_up_sync(0xffffffffu, s0, 1)
                     + __shfl_down_sync(0xffffffffu, s0, 1);
        C[1][k] = s1 + __shfl_up_sync(0xffffffffu, s1, 1)
                     + __shfl_down_sync(0xffffffffu, s1, 1);
        C[2][k] = s2 + __shfl_up_sync(0xffffffffu, s2, 1)
                     + __shfl_down_sync(0xffffffffu, s2, 1);
        C[3][k] = s3 + __shfl_up_sync(0xffffffffu, s3, 1)
                     + __shfl_down_sync(0xffffffffu, s3, 1);
    }
}

__global__ __launch_bounds__(128, 4)
void lncc_fused_kernel(const float* __restrict__ pred,
                       const float* __restrict__ targ,
                       float* __restrict__ out)
{
    const int lane = threadIdx.x;                       // 0..31 along d
    const int dcol = blockIdx.x * D_OUT + lane - 1;     // loaded d column
    const int h0   = blockIdx.y * (BY * H_OUT) + threadIdx.y * H_OUT;
    const int w0   = blockIdx.z * WCHUNK;

    const bool dok = (dcol >= 0) && (dcol < SZ);
    unsigned hmask = 0;
#pragma unroll
    for (int i = 0; i < 6; i++) {
        int hh = h0 - 1 + i;
        if (hh >= 0 && hh < SZ) hmask |= (1u << i);
    }
    const int base0 = (h0 - 1) * SZ2 + dcol;            // row0, plane 0 offset
    const bool emit_ok = (lane >= 1) && (lane <= D_OUT) && (dcol < SZ);

    float R[3][H_OUT][5];
    float acc = 0.f;
    const float inv_kv = 1.0f / 27.0f;

    // planes p = 0..17 -> wp = w0-1+p; stored in slot p%3.
    // emit at p>=2: output w = w0+p-2 uses slots (p-2)%3, (p-1)%3, p%3.
#define LNCC_STEP(P_, R_)                                                     \
    do {                                                                      \
        compute_plane(pred, targ, base0, w0 - 1 + (P_), hmask, dok, R[(R_)]); \
        if ((P_) >= 2 && emit_ok) {                                           \
            float (&A_)[H_OUT][5] = R[((R_) + 1) % 3];                        \
            float (&B_)[H_OUT][5] = R[((R_) + 2) % 3];                        \
            float (&C_)[H_OUT][5] = R[(R_)];                                  \
            _Pragma("unroll")                                                 \
            for (int j = 0; j < H_OUT; j++) {                                 \
                float sI  = A_[j][0] + B_[j][0] + C_[j][0];                   \
                float sJ  = A_[j][1] + B_[j][1] + C_[j][1];                   \
                float sII = A_[j][2] + B_[j][2] + C_[j][2];                   \
                float sJJ = A_[j][3] + B_[j][3] + C_[j][3];                   \
                float sIJ = A_[j][4] + B_[j][4] + C_[j][4];                   \
                float m1 = sI * inv_kv;                                       \
                float m2 = sJ * inv_kv;                                       \
                float cross = fmaf(-m2, sI, sIJ);                             \
                float Iv    = fmaf(-m1, sI, sII);                             \
                float Jv    = fmaf(-m2, sJ, sJJ);                             \
                float den   = fmaf(Iv, Jv, 1e-5f);                            \
                float num   = cross * cross;                                  \
                acc += __fdividef(num, den);                                  \
            }                                                                 \
        }                                                                     \
    } while (0)

    for (int t = 0; t < 6; t++) {
        int p = 3 * t;
        LNCC_STEP(p + 0, 0);
        LNCC_STEP(p + 1, 1);
        LNCC_STEP(p + 2, 2);
    }
#undef LNCC_STEP

    // ---- deterministic in-kernel reduction ----
    __shared__ float  sred[128];
    __shared__ double dred[128];
    __shared__ unsigned int s_last;
    const int tid = threadIdx.y * 32 + lane;

    sred[tid] = acc;
    __syncthreads();
#pragma unroll
    for (int s = 64; s > 0; s >>= 1) {
        if (tid < s) sred[tid] += sred[tid + s];
        __syncthreads();
    }
    if (tid == 0) {
        const int blin = blockIdx.x + GX * (blockIdx.y + GY * blockIdx.z);
        g_partial[blin] = sred[0];
        __threadfence();
        unsigned old = atomicAdd(&g_count, 1u);
        s_last = (old == (unsigned)(NBLK - 1)) ? 1u : 0u;
    }
    __syncthreads();

    if (s_last) {
        double s = 0.0;
        for (int i = tid; i < NBLK; i += 128)
            s += (double)g_partial[i];
        dred[tid] = s;
        __syncthreads();
#pragma unroll
        for (int k = 64; k > 0; k >>= 1) {
            if (tid < k) dred[tid] += dred[tid + k];
            __syncthreads();
        }
        if (tid == 0) {
            out[0] = (float)(-dred[0] / (double)NTOT);
            g_count = 0;   // reset for the next (graph-replayed) call
        }
    }
}

extern "C" void kernel_launch(void* const* d_in, const int* in_sizes, int n_in,
                              void* d_out, int out_size) {
    const float* pred = (const float*)d_in[0];
    const float* targ = (const float*)d_in[1];
    dim3 grid(GX, GY, GZ);
    dim3 block(32, BY, 1);
    lncc_fused_kernel<<<grid, block>>>(pred, targ, (float*)d_out);
}

// round 3
// speedup vs baseline: 2.1328x; 1.1822x over previous
#include <cuda_runtime.h>

// Fused local NCC loss (kernel=3, zero 'same' padding) over 192^3 f32 volumes.
// Lanes along d (coalesced), H_OUT=4 h-outputs per thread (rows streamed into
// sliding h-sums), w marched with a 3-slot plane ring, d-window via warp
// shuffles applied once per emitted output (after the w-sum).
// The 5 NCC components are packed: (I,J) and (I*I,J*J) as f32x2, I*J scalar.

#define SZ   192
#define SZ2  (SZ * SZ)
#define NTOT (SZ * SZ * SZ)

#define D_OUT  30             // d outputs per warp (lanes 1..30)
#define GX     7              // ceil(192/30)
#define H_OUT  4              // h outputs per thread
#define BY     4              // h-groups per block -> h tile 16
#define GY     12             // 192/16
#define WCHUNK 16             // w outputs per block
#define GZ     12             // 192/16
#define NBLK   (GX * GY * GZ) // 1008

typedef unsigned long long u64;

__device__ float        g_partial[NBLK];
__device__ unsigned int g_count = 0;

__device__ __forceinline__ u64 pk2(float lo, float hi) {
    u64 r; asm("mov.b64 %0, {%1, %2};" : "=l"(r) : "f"(lo), "f"(hi)); return r;
}
__device__ __forceinline__ void upk2(u64 v, float& lo, float& hi) {
    asm("mov.b64 {%0, %1}, %2;" : "=f"(lo), "=f"(hi) : "l"(v));
}
__device__ __forceinline__ u64 add2(u64 a, u64 b) {
    u64 r; asm("add.rn.f32x2 %0, %1, %2;" : "=l"(r) : "l"(a), "l"(b)); return r;
}
__device__ __forceinline__ u64 mul2(u64 a, u64 b) {
    u64 r; asm("mul.rn.f32x2 %0, %1, %2;" : "=l"(r) : "l"(a), "l"(b)); return r;
}

struct Plane {
    u64   P[H_OUT];   // packed (sumI, sumJ) over 3x... h window (d,w not yet summed)
    u64   Q[H_OUT];   // packed (sumII, sumJJ)
    float R[H_OUT];   // sumIJ
};

__device__ __forceinline__ void compute_plane(
    const float* __restrict__ pred, const float* __restrict__ targ,
    int base0, int wp, unsigned m, Plane& C)
{
    if ((unsigned)wp >= (unsigned)SZ) {
        #pragma unroll
        for (int j = 0; j < H_OUT; j++) { C.P[j] = 0ull; C.Q[j] = 0ull; C.R[j] = 0.f; }
        return;
    }
    const int pofs = base0 + wp * SZ;
    #pragma unroll
    for (int i = 0; i < 6; i++) {
        float I = 0.f, J = 0.f;
        if ((m >> i) & 1u) {
            const int o = pofs + i * SZ2;
            I = pred[o];
            J = targ[o];
        }
        u64 p = pk2(I, J);
        u64 q = mul2(p, p);
        float r = I * J;
        if (i == 0) { C.P[0] = p; C.Q[0] = q; C.R[0] = r; }
        if (i == 1) {
            C.P[0] = add2(C.P[0], p); C.Q[0] = add2(C.Q[0], q); C.R[0] += r;
            C.P[1] = p; C.Q[1] = q; C.R[1] = r;
        }
        if (i == 2) {
            C.P[0] = add2(C.P[0], p); C.Q[0] = add2(C.Q[0], q); C.R[0] += r;
            C.P[1] = add2(C.P[1], p); C.Q[1] = add2(C.Q[1], q); C.R[1] += r;
            C.P[2] = p; C.Q[2] = q; C.R[2] = r;
        }
        if (i == 3) {
            C.P[1] = add2(C.P[1], p); C.Q[1] = add2(C.Q[1], q); C.R[1] += r;
            C.P[2] = add2(C.P[2], p); C.Q[2] = add2(C.Q[2], q); C.R[2] += r;
            C.P[3] = p; C.Q[3] = q; C.R[3] = r;
        }
        if (i == 4) {
            C.P[2] = add2(C.P[2], p); C.Q[2] = add2(C.Q[2], q); C.R[2] += r;
            C.P[3] = add2(C.P[3], p); C.Q[3] = add2(C.Q[3], q); C.R[3] += r;
        }
        if (i == 5) {
            C.P[3] = add2(C.P[3], p); C.Q[3] = add2(C.Q[3], q); C.R[3] += r;
        }
    }
}

// Runs on ALL lanes (contains warp shuffles). Caller predicates accumulation.
__device__ __forceinline__ float emit3(const Plane& A, const Plane& B, const Plane& C)
{
    float v = 0.f;
    const float inv_kv = 1.0f / 27.0f;
    #pragma unroll
    for (int j = 0; j < H_OUT; j++) {
        u64   Pw = add2(add2(A.P[j], B.P[j]), C.P[j]);
        u64   Qw = add2(add2(A.Q[j], B.Q[j]), C.Q[j]);
        float Rw = A.R[j] + B.R[j] + C.R[j];
        // d-window: lanes hold consecutive d columns
        u64 Pu = __shfl_up_sync(0xffffffffu, Pw, 1);
        u64 Pd = __shfl_down_sync(0xffffffffu, Pw, 1);
        Pw = add2(add2(Pu, Pw), Pd);
        u64 Qu = __shfl_up_sync(0xffffffffu, Qw, 1);
        u64 Qd = __shfl_down_sync(0xffffffffu, Qw, 1);
        Qw = add2(add2(Qu, Qw), Qd);
        float Ru = __shfl_up_sync(0xffffffffu, Rw, 1);
        float Rd = __shfl_down_sync(0xffffffffu, Rw, 1);
        Rw = Ru + Rw + Rd;

        float sI, sJ, sII, sJJ;
        upk2(Pw, sI, sJ);
        upk2(Qw, sII, sJJ);
        float m1 = sI * inv_kv;
        float m2 = sJ * inv_kv;
        float cross = fmaf(-m2, sI, Rw);    // sum((I-uI)(J-uJ))
        float Iv    = fmaf(-m1, sI, sII);   // sum((I-uI)^2)
        float Jv    = fmaf(-m2, sJ, sJJ);   // sum((J-uJ)^2)
        float den   = fmaf(Iv, Jv, 1e-5f);
        v += __fdividef(cross * cross, den);
    }
    return v;
}

__global__ __launch_bounds__(128, 5)
void lncc_fused_kernel(const float* __restrict__ pred,
                       const float* __restrict__ targ,
                       float* __restrict__ out)
{
    const int lane = threadIdx.x;                       // 0..31 along d
    const int dcol = blockIdx.x * D_OUT + lane - 1;     // loaded d column
    const int h0   = blockIdx.y * (BY * H_OUT) + threadIdx.y * H_OUT;
    const int w0   = blockIdx.z * WCHUNK;

    const bool dok = (dcol >= 0) && (dcol < SZ);
    unsigned m = 0;
    #pragma unroll
    for (int i = 0; i < 6; i++) {
        int hh = h0 - 1 + i;
        if (dok && hh >= 0 && hh < SZ) m |= (1u << i);
    }
    const int  base0   = (h0 - 1) * SZ2 + dcol;
    const bool emit_ok = (lane >= 1) && (lane <= D_OUT) && (dcol < SZ);

    Plane S[3];
    float acc = 0.f;
    int wp = w0 - 1;

#define STEPC(SLOT) do { compute_plane(pred, targ, base0, wp, m, S[SLOT]); wp++; } while (0)
#define STEPE(SLOT) do {                                                      \
        compute_plane(pred, targ, base0, wp, m, S[SLOT]); wp++;               \
        float v_ = emit3(S[((SLOT) + 1) % 3], S[((SLOT) + 2) % 3], S[SLOT]);  \
        if (emit_ok) acc += v_;                                               \
    } while (0)

    STEPC(0);
    STEPC(1);
    STEPE(2);
    for (int t = 0; t < 4; t++) { STEPE(0); STEPE(1); STEPE(2); }
    STEPE(0); STEPE(1); STEPE(2);

#undef STEPC
#undef STEPE

    // ---- deterministic in-kernel reduction ----
    __shared__ float  sred[128];
    __shared__ double dred[128];
    __shared__ unsigned int s_last;
    const int tid = threadIdx.y * 32 + lane;

    sred[tid] = acc;
    __syncthreads();
    #pragma unroll
    for (int s = 64; s > 0; s >>= 1) {
        if (tid < s) sred[tid] += sred[tid + s];
        __syncthreads();
    }
    if (tid == 0) {
        const int blin = blockIdx.x + GX * (blockIdx.y + GY * blockIdx.z);
        g_partial[blin] = sred[0];
        __threadfence();
        unsigned old = atomicAdd(&g_count, 1u);
        s_last = (old == (unsigned)(NBLK - 1)) ? 1u : 0u;
    }
    __syncthreads();

    if (s_last) {
        double s = 0.0;
        for (int i = tid; i < NBLK; i += 128)
            s += (double)g_partial[i];
        dred[tid] = s;
        __syncthreads();
        #pragma unroll
        for (int k = 64; k > 0; k >>= 1) {
            if (tid < k) dred[tid] += dred[tid + k];
            __syncthreads();
        }
        if (tid == 0) {
            out[0] = (float)(-dred[0] / (double)NTOT);
            g_count = 0;   // reset for the next (graph-replayed) call
        }
    }
}

extern "C" void kernel_launch(void* const* d_in, const int* in_sizes, int n_in,
                              void* d_out, int out_size) {
    const float* pred = (const float*)d_in[0];
    const float* targ = (const float*)d_in[1];
    dim3 grid(GX, GY, GZ);
    dim3 block(32, BY, 1);
    lncc_fused_kernel<<<grid, block>>>(pred, targ, (float*)d_out);
}